// round 15
// baseline (speedup 1.0000x reference)
#include <cuda_runtime.h>
#include <cstdint>

typedef unsigned short u16;
typedef unsigned int   u32;
typedef unsigned char  u8;
typedef signed char    s8;

// ===========================================================================
// XNOR-net CNN forward via int8 mma.sync implicit GEMM (tensor pipe).
// Acts: s8 +-1 with 0 halo, layout [img][(W+2)^2][Cin], 64-px zero pads at
// both ends (zero-init at load, halo never written -> stays 0).
// Weights: s8 +-1 pre-arranged in m16n8k32 B-fragment-linear order.
// All binary-conv math is integer-exact vs the reference.
// ===========================================================================

#define PADPX 64

__device__ __align__(16) s8 g_act1[(128 * 1156 + 2 * PADPX) * 128];
__device__ __align__(16) s8 g_act2[(128 * 324  + 2 * PADPX) * 128];
__device__ __align__(16) s8 g_act3[(128 * 324  + 2 * PADPX) * 256];
__device__ __align__(16) s8 g_act4[(128 * 100  + 2 * PADPX) * 256];
__device__ __align__(16) s8 g_act5[(128 * 100  + 2 * PADPX) * 512];
__device__ __align__(16) u16 g_cnt[128 * 32 * 32 * 128];   // relu'd counts scratch
__device__ float g_h6[128 * 4 * 4 * 512];

// B-fragment weights: unit = ((tap*(COUT/8)+cg)*(CIN/32)+kc)*256 + lane*8 bytes
__device__ __align__(16) s8 g_fb2[9 * 128 * 128];
__device__ __align__(16) s8 g_fb3[9 * 256 * 128];
__device__ __align__(16) s8 g_fb4[9 * 256 * 256];
__device__ __align__(16) s8 g_fb5[9 * 512 * 256];
__device__ __align__(16) s8 g_fb6[9 * 512 * 512];

// ---------------------------------------------------------------------------
// mma.sync m16n8k32 s8 x s8 -> s32 (row.col). Standard sm_80+ fragment maps.
// ---------------------------------------------------------------------------
__device__ __forceinline__ void mma_s8(int* c, u32 a0, u32 a1, u32 a2, u32 a3,
                                       u32 b0, u32 b1)
{
    asm volatile(
        "mma.sync.aligned.m16n8k32.row.col.s32.s8.s8.s32 "
        "{%0,%1,%2,%3}, {%4,%5,%6,%7}, {%8,%9}, {%0,%1,%2,%3};"
        : "+r"(c[0]), "+r"(c[1]), "+r"(c[2]), "+r"(c[3])
        : "r"(a0), "r"(a1), "r"(a2), "r"(a3), "r"(b0), "r"(b1));
}

// ===========================================================================
// Weight pack -> B-fragment order, all 5 layers in one launch.
// w is HWIO float [3][3][Cin][Cout], tap t = ky*3+kx.
// Fragment byte map (thread t32 of the consuming warp):
//   n = cg*8 + t32/4, tig = t32%4
//   reg0 bytes j=0..3: B[n][k = kc*32 + 4*tig + j]
//   reg1 bytes j=0..3: B[n][k = kc*32 + 16 + 4*tig + j]
// ===========================================================================
__device__ __forceinline__ void packb(const float* __restrict__ w, s8* out,
                                      int Cin, int Cout, int unit)
{
    int t32 = unit & 31;
    int q = unit >> 5;
    int kcn = Cin >> 5;
    int kc = q % kcn; q /= kcn;
    int cgn = Cout >> 3;
    int cg = q % cgn;
    int tap = q / cgn;
    int n = cg * 8 + (t32 >> 2), tig = t32 & 3;
    u32 lo = 0, hi = 0;
#pragma unroll
    for (int j = 0; j < 4; j++) {
        int k0 = kc * 32 + 4 * tig + j;
        u32 blo = (w[(size_t)(tap * Cin + k0) * Cout + n] > 0.f) ? 0x01u : 0xFFu;
        u32 bhi = (w[(size_t)(tap * Cin + k0 + 16) * Cout + n] > 0.f) ? 0x01u : 0xFFu;
        lo |= blo << (8 * j);
        hi |= bhi << (8 * j);
    }
    *reinterpret_cast<uint2*>(out + (size_t)unit * 8) = make_uint2(lo, hi);
}

__global__ void __launch_bounds__(256) packb_kernel(
    const float* __restrict__ w2, const float* __restrict__ w3,
    const float* __restrict__ w4, const float* __restrict__ w5,
    const float* __restrict__ w6)
{
    int idx = blockIdx.x * 256 + threadIdx.x;
    // 8-byte units per layer: 9*COUT*CIN/8
    if (idx < 18432)        packb(w2, g_fb2, 128, 128, idx);
    else if (idx < 55296)   packb(w3, g_fb3, 128, 256, idx - 18432);
    else if (idx < 129024)  packb(w4, g_fb4, 256, 256, idx - 55296);
    else if (idx < 276480)  packb(w5, g_fb5, 256, 512, idx - 129024);
    else if (idx < 571392)  packb(w6, g_fb6, 512, 512, idx - 276480);
}

// ===========================================================================
// conv1 (float) + relu + bn + sign -> s8 +-1 halo tensor g_act1
// ===========================================================================
__global__ void __launch_bounds__(128) conv1_kernel(
    const float* __restrict__ x, const float* __restrict__ w1,
    const float* __restrict__ b1, const float* __restrict__ s1,
    const float* __restrict__ bi1)
{
    __shared__ __align__(16) float sw[27 * 128];
    __shared__ float sb[128], ss[128], sbi[128];
    int tid = threadIdx.x;
    for (int i = tid; i < 27 * 128; i += 128) sw[i] = w1[i];
    sb[tid] = b1[tid]; ss[tid] = s1[tid]; sbi[tid] = bi1[tid];
    __syncthreads();

    int pid = blockIdx.x * 128 + tid;
    int b = pid >> 10, y = (pid >> 5) & 31, xx = pid & 31;

    float in[27];
#pragma unroll
    for (int dy = 0; dy < 3; dy++)
#pragma unroll
        for (int dx = 0; dx < 3; dx++) {
            int iy = y + dy - 1, ix = xx + dx - 1;
            bool v = (iy >= 0 && iy < 32 && ix >= 0 && ix < 32);
            const float* p = x + ((b * 32 + iy) * 32 + ix) * 3;
#pragma unroll
            for (int c = 0; c < 3; c++)
                in[(dy * 3 + dx) * 3 + c] = v ? p[c] : 0.f;
        }

    s8* dst = g_act1 + ((size_t)PADPX + (size_t)b * 1156 + (y + 1) * 34 + (xx + 1)) * 128;
#pragma unroll
    for (int chunk = 0; chunk < 4; chunk++) {
        u32 wb[8];
#pragma unroll
        for (int jj = 0; jj < 8; jj++) {
            int co4 = chunk * 32 + jj * 4;
            float4 acc = make_float4(0.f, 0.f, 0.f, 0.f);
#pragma unroll
            for (int k = 0; k < 27; k++) {
                float4 wv = *reinterpret_cast<const float4*>(&sw[k * 128 + co4]);
                float iv = in[k];
                acc.x = fmaf(iv, wv.x, acc.x);
                acc.y = fmaf(iv, wv.y, acc.y);
                acc.z = fmaf(iv, wv.z, acc.z);
                acc.w = fmaf(iv, wv.w, acc.w);
            }
            float av[4] = {acc.x, acc.y, acc.z, acc.w};
            u32 word = 0;
#pragma unroll
            for (int e = 0; e < 4; e++) {
                int co = co4 + e;
                float v = fmaxf(av[e] + sb[co], 0.f);
                u32 o = (fmaf(v, ss[co], sbi[co]) > 0.f) ? 0x01u : 0xFFu;
                word |= o << (8 * e);
            }
            wb[jj] = word;
        }
        uint4* d4 = reinterpret_cast<uint4*>(dst + chunk * 32);
        d4[0] = make_uint4(wb[0], wb[1], wb[2], wb[3]);
        d4[1] = make_uint4(wb[4], wb[5], wb[6], wb[7]);
    }
}

// ===========================================================================
// Binary conv via int8 mma.sync implicit GEMM.
// CTA: 512 threads = 16 warps = 8 m-bands x 2 n-halves.
// Tile: M=128 halo pixels x N=min(COUT,256) (gridDim.y = COUT/N).
// K: 9 taps x CIN, 32/step. Act staged in smem (row stride CIN+16: no bank
// conflicts). B read straight from fragment-linear gmem (L2-resident).
// ===========================================================================
template <int W, int CIN, int COUT, bool POOL, int LAYER>
__global__ void __launch_bounds__(512) bconv_imma_kernel(
    const float* __restrict__ bn_s, const float* __restrict__ bn_b)
{
    constexpr int HP = (W + 2) * (W + 2);
    constexpr int EXT = W + 3;
    constexpr int STPX = 128 + 2 * EXT;
    constexpr int RS = CIN + 16;            // stage row stride (bank-spread)
    constexpr int KC = CIN / 32;
    constexpr int NCTA = (COUT > 256) ? 256 : COUT;
    constexpr int NW = NCTA / 2;            // n-range per warp
    constexpr int NCH = NW / 8;             // n8 chunks per warp

    extern __shared__ __align__(16) s8 st[];

    const int tid = threadIdx.x, lane = tid & 31, wp = tid >> 5;
    const int mband = wp & 7, nhalf = wp >> 3;

    const s8 *act_in, *fb;
    s8* outp = nullptr;
    if constexpr (LAYER == 2)      { act_in = g_act1 + (size_t)PADPX * CIN; fb = g_fb2; }
    else if constexpr (LAYER == 3) { act_in = g_act2 + (size_t)PADPX * CIN; fb = g_fb3;
                                     outp = g_act3 + (size_t)PADPX * COUT; }
    else if constexpr (LAYER == 4) { act_in = g_act3 + (size_t)PADPX * CIN; fb = g_fb4; }
    else if constexpr (LAYER == 5) { act_in = g_act4 + (size_t)PADPX * CIN; fb = g_fb5;
                                     outp = g_act5 + (size_t)PADPX * COUT; }
    else                           { act_in = g_act5 + (size_t)PADPX * CIN; fb = g_fb6; }

    const int m0 = blockIdx.x * 128;
    const int nbc = blockIdx.y * NCTA;

    // ---- stage act region [m0-EXT, m0+128+EXT) into smem ----
    {
        constexpr int C16 = CIN / 16;
        const uint4* src = reinterpret_cast<const uint4*>(act_in + (size_t)(m0 - EXT) * CIN);
        for (int i = tid; i < STPX * C16; i += 512) {
            int r = i / C16, cb = i % C16;
            *reinterpret_cast<uint4*>(st + r * RS + cb * 16) = src[i];
        }
    }
    __syncthreads();

    int C[NCH][4];
#pragma unroll
    for (int c = 0; c < NCH; c++) { C[c][0] = C[c][1] = C[c][2] = C[c][3] = 0; }

    const int nb = nbc + nhalf * NW;
    const int rb0 = EXT + mband * 16 + (lane >> 2);
    const int kb = 4 * (lane & 3);

#pragma unroll
    for (int t = 0; t < 9; t++) {
        const int off = (t / 3 - 1) * (W + 2) + (t % 3) - 1;
        const s8* r0 = st + (rb0 + off) * RS + kb;
        const s8* fbt = fb + ((size_t)t * (COUT / 8) + (nb >> 3)) * KC * 256 + lane * 8;
#pragma unroll
        for (int kc = 0; kc < KC; kc++) {
            u32 a0 = *reinterpret_cast<const u32*>(r0 + kc * 32);
            u32 a1 = *reinterpret_cast<const u32*>(r0 + 8 * RS + kc * 32);
            u32 a2 = *reinterpret_cast<const u32*>(r0 + kc * 32 + 16);
            u32 a3 = *reinterpret_cast<const u32*>(r0 + 8 * RS + kc * 32 + 16);
            const s8* bp = fbt + kc * 256;
#pragma unroll
            for (int c = 0; c < NCH; c++) {
                uint2 bv = *reinterpret_cast<const uint2*>(bp + (size_t)c * KC * 256);
                mma_s8(C[c], a0, a1, a2, a3, bv.x, bv.y);
            }
        }
    }

    // ---- epilogue: C[c][2h+j] = (row mband*16+lane/4+8h, col nb+c*8+2*(lane%4)+j)
    const int pr0 = m0 + mband * 16 + (lane >> 2);
    const int tig2 = 2 * (lane & 3);
#pragma unroll
    for (int half = 0; half < 2; half++) {
        const int p = pr0 + half * 8;
        const int img = p / HP, pp = p % HP;
        const int yy = pp / (W + 2), xx = pp % (W + 2);
        if (yy < 1 || yy > W || xx < 1 || xx > W) continue;
        if constexpr (POOL) {
            u16* crow = g_cnt + (((size_t)img * W + (yy - 1)) * W + (xx - 1)) * COUT;
#pragma unroll
            for (int c = 0; c < NCH; c++) {
                int n0 = nb + c * 8 + tig2;
                u32 v0 = (u32)(u16)max(C[c][half * 2 + 0], 0);
                u32 v1 = (u32)(u16)max(C[c][half * 2 + 1], 0);
                *reinterpret_cast<u32*>(crow + n0) = v0 | (v1 << 16);
            }
        } else {
            s8* orow = outp + (size_t)p * COUT;
#pragma unroll
            for (int c = 0; c < NCH; c++) {
                int n0 = nb + c * 8 + tig2;
                float s0 = fmaxf((float)C[c][half * 2 + 0], 0.f);
                float s1 = fmaxf((float)C[c][half * 2 + 1], 0.f);
                u32 b0 = (fmaf(s0, bn_s[n0], bn_b[n0]) > 0.f) ? 0x01u : 0xFFu;
                u32 b1 = (fmaf(s1, bn_s[n0 + 1], bn_b[n0 + 1]) > 0.f) ? 0x01u : 0xFFu;
                *reinterpret_cast<u16*>(orow + n0) = (u16)(b0 | (b1 << 8));
            }
        }
    }
}

// ===========================================================================
// 2x2 maxpool on u16 counts + BN (+sign -> s8 halo tensor, or float for L6)
// ===========================================================================
template <int WIN, int COUT, int LAYER>
__global__ void __launch_bounds__(256) pool_kernel(
    const float* __restrict__ bn_s, const float* __restrict__ bn_b)
{
    constexpr int WOUT = WIN / 2, HPN = (WOUT + 2) * (WOUT + 2), C2 = COUT / 2;
    int idx = blockIdx.x * 256 + threadIdx.x;
    if (idx >= 128 * WOUT * WOUT * C2) return;
    int c2 = idx % C2; int q = idx / C2;
    int x = q % WOUT; q /= WOUT;
    int y = q % WOUT; int img = q / WOUT;

    const u32* cin = reinterpret_cast<const u32*>(g_cnt);
    size_t base = ((size_t)img * WIN + 2 * y) * WIN + 2 * x;
    u32 v00 = cin[(base) * C2 + c2];
    u32 v01 = cin[(base + 1) * C2 + c2];
    u32 v10 = cin[(base + WIN) * C2 + c2];
    u32 v11 = cin[(base + WIN + 1) * C2 + c2];
    int lo = max(max((int)(v00 & 0xFFFF), (int)(v01 & 0xFFFF)),
                 max((int)(v10 & 0xFFFF), (int)(v11 & 0xFFFF)));
    int hi = max(max((int)(v00 >> 16), (int)(v01 >> 16)),
                 max((int)(v10 >> 16), (int)(v11 >> 16)));
    int c = 2 * c2;
    if constexpr (LAYER == 6) {
        float* o = g_h6 + (((size_t)img * 4 + y) * 4 + x) * 512 + c;
        o[0] = fmaf((float)lo, bn_s[c], bn_b[c]);
        o[1] = fmaf((float)hi, bn_s[c + 1], bn_b[c + 1]);
    } else {
        u32 b0 = (fmaf((float)lo, bn_s[c], bn_b[c]) > 0.f) ? 0x01u : 0xFFu;
        u32 b1 = (fmaf((float)hi, bn_s[c + 1], bn_b[c + 1]) > 0.f) ? 0x01u : 0xFFu;
        s8* dst = (LAYER == 2 ? g_act2 : g_act4)
                  + ((size_t)PADPX + (size_t)img * HPN + (y + 1) * (WOUT + 2) + (x + 1)) * COUT + c;
        *reinterpret_cast<u16*>(dst) = (u16)(b0 | (b1 << 8));
    }
}

// ===========================================================================
// Dense (512->10) + softmax
// ===========================================================================
__global__ void __launch_bounds__(128) dense_softmax_kernel(
    const float* __restrict__ dw, const float* __restrict__ db, float* __restrict__ out)
{
    __shared__ float sdw[512 * 10];
    __shared__ float sdb[10];
    int tid = threadIdx.x;
    for (int i = tid; i < 5120; i += 128) sdw[i] = dw[i];
    if (tid < 10) sdb[tid] = db[tid];
    __syncthreads();

    int r = blockIdx.x * 128 + tid;
    float acc[10];
#pragma unroll
    for (int d = 0; d < 10; d++) acc[d] = sdb[d];
    const float* h = g_h6 + (size_t)r * 512;
    for (int c = 0; c < 512; c++) {
        float hv = h[c];
#pragma unroll
        for (int d = 0; d < 10; d++) acc[d] = fmaf(hv, sdw[c * 10 + d], acc[d]);
    }
    float m = acc[0];
#pragma unroll
    for (int d = 1; d < 10; d++) m = fmaxf(m, acc[d]);
    float e[10], s = 0.f;
#pragma unroll
    for (int d = 0; d < 10; d++) { e[d] = expf(acc[d] - m); s += e[d]; }
    float inv = 1.f / s;
#pragma unroll
    for (int d = 0; d < 10; d++) out[r * 10 + d] = e[d] * inv;
}

// ===========================================================================
// Launch
// ===========================================================================
extern "C" void kernel_launch(void* const* d_in, const int* in_sizes, int n_in,
                              void* d_out, int out_size)
{
    const float *x = nullptr, *w1 = nullptr, *b1 = nullptr;
    const float *w2 = nullptr, *w3 = nullptr, *w4 = nullptr, *w5 = nullptr, *w6 = nullptr;
    const float *dw = nullptr, *db = nullptr;
    const float* bns[12] = {nullptr};
    int bn_idx = 0;

    for (int i = 0; i < n_in; i++) {
        const float* p = (const float*)d_in[i];
        int s = in_sizes[i];
        if (i == 0)              x = p;
        else if (s == 3456)      w1 = p;
        else if (i == 2)         b1 = p;
        else if (s == 147456)    w2 = p;
        else if (s == 294912)    w3 = p;
        else if (s == 589824)    w4 = p;
        else if (s == 1179648)   w5 = p;
        else if (s == 2359296)   w6 = p;
        else if (s == 5120)      dw = p;
        else if (s == 10)        db = p;
        else if (bn_idx < 12)    bns[bn_idx++] = p;
    }

    // dynamic smem: (128 + 2*(W+3)) rows x (CIN+16) bytes
    const int SM_L2 = 198 * 144;   // 28512
    const int SM_L3 = 166 * 144;   // 23904
    const int SM_L4 = 166 * 272;   // 45152
    const int SM_L5 = 150 * 272;   // 40800
    const int SM_L6 = 150 * 528;   // 79200
    cudaFuncSetAttribute(bconv_imma_kernel<32, 128, 128, true,  2>,
                         cudaFuncAttributeMaxDynamicSharedMemorySize, SM_L2);
    cudaFuncSetAttribute(bconv_imma_kernel<16, 128, 256, false, 3>,
                         cudaFuncAttributeMaxDynamicSharedMemorySize, SM_L3);
    cudaFuncSetAttribute(bconv_imma_kernel<16, 256, 256, true,  4>,
                         cudaFuncAttributeMaxDynamicSharedMemorySize, SM_L4);
    cudaFuncSetAttribute(bconv_imma_kernel<8, 256, 512, false, 5>,
                         cudaFuncAttributeMaxDynamicSharedMemorySize, SM_L5);
    cudaFuncSetAttribute(bconv_imma_kernel<8, 512, 512, true,  6>,
                         cudaFuncAttributeMaxDynamicSharedMemorySize, SM_L6);

    conv1_kernel<<<1024, 128>>>(x, w1, b1, bns[0], bns[1]);
    packb_kernel<<<(571392 + 255) / 256, 256>>>(w2, w3, w4, w5, w6);

    bconv_imma_kernel<32, 128, 128, true,  2><<<dim3(1156, 1), 512, SM_L2>>>(bns[2], bns[3]);
    pool_kernel<32, 128, 2><<<8192, 256>>>(bns[2], bns[3]);
    bconv_imma_kernel<16, 128, 256, false, 3><<<dim3(324, 1), 512, SM_L3>>>(bns[4], bns[5]);
    bconv_imma_kernel<16, 256, 256, true,  4><<<dim3(324, 1), 512, SM_L4>>>(bns[6], bns[7]);
    pool_kernel<16, 256, 4><<<4096, 256>>>(bns[6], bns[7]);
    bconv_imma_kernel<8, 256, 512, false, 5><<<dim3(100, 2), 512, SM_L5>>>(bns[8], bns[9]);
    bconv_imma_kernel<8, 512, 512, true,  6><<<dim3(100, 2), 512, SM_L6>>>(bns[10], bns[11]);
    pool_kernel<8, 512, 6><<<2048, 256>>>(bns[10], bns[11]);

    dense_softmax_kernel<<<16, 128>>>(dw, db, (float*)d_out);
    (void)out_size;
}

// round 16
// speedup vs baseline: 2.7708x; 2.7708x over previous
#include <cuda_runtime.h>
#include <cstdint>

typedef unsigned int u32;

// ---------------------------------------------------------------------------
// XNOR-net CNN forward, GB300. Binary convs exact via bitpack + popcount.
// cp.async double-buffered per-image pipeline, 256-thread CTAs.
// Intermediates are 1-bit tensors in __device__ globals (no allocations).
// ---------------------------------------------------------------------------

// Bit tensors: layout [b][y][x][cw], bit j of word cw = channel cw*32+j
__device__ __align__(16) unsigned g_bits1[128 * 32 * 32 * 4];
__device__ __align__(16) unsigned g_bits2[128 * 16 * 16 * 4];
__device__ __align__(16) unsigned g_bits3[128 * 16 * 16 * 8];
__device__ __align__(16) unsigned g_bits4[128 * 8 * 8 * 8];
__device__ __align__(16) unsigned g_bits5[128 * 8 * 8 * 16];
__device__ float g_h6[128 * 4 * 4 * 512];

// Packed weights: uint4 index [(t*G + g)*COUT + co] holds cin-words g*4..g*4+3
__device__ __align__(16) unsigned g_pw2[9 * 4 * 128];
__device__ __align__(16) unsigned g_pw3[9 * 4 * 256];
__device__ __align__(16) unsigned g_pw4[9 * 8 * 256];
__device__ __align__(16) unsigned g_pw5[9 * 8 * 512];
__device__ __align__(16) unsigned g_pw6[9 * 16 * 512];

// ---------------------------------------------------------------------------
// cp.async helpers
// ---------------------------------------------------------------------------
__device__ __forceinline__ void cp16(u32 sa, const void* g)
{
    asm volatile("cp.async.cg.shared.global [%0], [%1], 16;"
                 :: "r"(sa), "l"(g) : "memory");
}
#define CP_COMMIT() asm volatile("cp.async.commit_group;" ::: "memory")
#define CP_WAIT0()  asm volatile("cp.async.wait_group 0;" ::: "memory")

// ---------------------------------------------------------------------------
// Weight bit-packing (R11 layout), all 5 layers in one launch.
// ---------------------------------------------------------------------------
__device__ __forceinline__ void pack_one(const float* __restrict__ w, unsigned* out,
                                         int Cin, int Cout, int rel)
{
    int co = rel % Cout;
    int q = rel / Cout;
    int cwn = Cin >> 5;
    int cw = q % cwn;
    int t = q / cwn;
    unsigned word = 0;
#pragma unroll 8
    for (int j = 0; j < 32; j++) {
        float v = w[(t * Cin + cw * 32 + j) * Cout + co];
        word |= (v > 0.f ? 1u : 0u) << j;
    }
    int G = cwn >> 2;
    int g = cw >> 2, k = cw & 3;
    out[((t * G + g) * Cout + co) * 4 + k] = word;
}

__global__ void __launch_bounds__(256) pack_all_kernel(
    const float* __restrict__ w2, const float* __restrict__ w3,
    const float* __restrict__ w4, const float* __restrict__ w5,
    const float* __restrict__ w6)
{
    int idx = blockIdx.x * 256 + threadIdx.x;
    if (idx < 4608)        pack_one(w2, g_pw2, 128, 128, idx);
    else if (idx < 13824)  pack_one(w3, g_pw3, 128, 256, idx - 4608);
    else if (idx < 32256)  pack_one(w4, g_pw4, 256, 256, idx - 13824);
    else if (idx < 69120)  pack_one(w5, g_pw5, 256, 512, idx - 32256);
    else if (idx < 142848) pack_one(w6, g_pw6, 512, 512, idx - 69120);
}

// ---------------------------------------------------------------------------
// conv1: fp32 3x3 conv 3->128 SAME, +b1, relu, BN, sign -> bitpack
// ---------------------------------------------------------------------------
__global__ void __launch_bounds__(128) conv1_kernel(
    const float* __restrict__ x, const float* __restrict__ w1,
    const float* __restrict__ b1, const float* __restrict__ s1,
    const float* __restrict__ bi1)
{
    __shared__ __align__(16) float sw[27 * 128];
    __shared__ float sb[128], ss[128], sbi[128];
    int tid = threadIdx.x;
    for (int i = tid; i < 27 * 128; i += 128) sw[i] = w1[i];
    sb[tid] = b1[tid]; ss[tid] = s1[tid]; sbi[tid] = bi1[tid];
    __syncthreads();

    int pid = blockIdx.x * 128 + tid;
    int b = pid >> 10, y = (pid >> 5) & 31, xx = pid & 31;

    float in[27];
#pragma unroll
    for (int dy = 0; dy < 3; dy++)
#pragma unroll
        for (int dx = 0; dx < 3; dx++) {
            int iy = y + dy - 1, ix = xx + dx - 1;
            bool v = (iy >= 0 && iy < 32 && ix >= 0 && ix < 32);
            const float* p = x + ((b * 32 + iy) * 32 + ix) * 3;
#pragma unroll
            for (int c = 0; c < 3; c++)
                in[(dy * 3 + dx) * 3 + c] = v ? p[c] : 0.f;
        }

#pragma unroll
    for (int chunk = 0; chunk < 4; chunk++) {
        unsigned word = 0;
#pragma unroll
        for (int jj = 0; jj < 8; jj++) {
            int co4 = chunk * 32 + jj * 4;
            float4 acc = make_float4(0.f, 0.f, 0.f, 0.f);
#pragma unroll
            for (int k = 0; k < 27; k++) {
                float4 wv = *reinterpret_cast<const float4*>(&sw[k * 128 + co4]);
                float iv = in[k];
                acc.x = fmaf(iv, wv.x, acc.x);
                acc.y = fmaf(iv, wv.y, acc.y);
                acc.z = fmaf(iv, wv.z, acc.z);
                acc.w = fmaf(iv, wv.w, acc.w);
            }
            float av[4] = {acc.x, acc.y, acc.z, acc.w};
#pragma unroll
            for (int e = 0; e < 4; e++) {
                int co = co4 + e;
                float v = fmaxf(av[e] + sb[co], 0.f);
                bool bit = fmaf(v, ss[co], sbi[co]) > 0.f;
                word |= (bit ? 1u : 0u) << (jj * 4 + e);
            }
        }
        g_bits1[pid * 4 + chunk] = word;
    }
}

// ---------------------------------------------------------------------------
// Common helpers
// ---------------------------------------------------------------------------
__device__ __forceinline__ int border_corr(int y, int x, int H, int W, const int S[9])
{
    int c = 0;
    if (y == 0)      c += S[0] + S[1] + S[2];
    if (y == H - 1)  c += S[6] + S[7] + S[8];
    if (x == 0) {
        c += S[0] + S[3] + S[6];
        if (y == 0)     c -= S[0];
        if (y == H - 1) c -= S[6];
    }
    if (x == W - 1) {
        c += S[2] + S[5] + S[8];
        if (y == 0)     c -= S[2];
        if (y == H - 1) c -= S[8];
    }
    return c;
}

__device__ __forceinline__ int popc4x(uint4 a, uint4 w)
{
    return __popc(a.x ^ w.x) + __popc(a.y ^ w.y) + __popc(a.z ^ w.z) + __popc(a.w ^ w.w);
}

// ---------------------------------------------------------------------------
// Binary conv, cp.async double-buffered image pipeline. 256 threads, 8 warps.
// Warp = 32 couts (lane = co). WREG: weights register-resident (G==1 layers);
// otherwise weights in smem. Non-pool G==1 uses pixel-pair interleave.
// ---------------------------------------------------------------------------
template <int W, int CW, int COUT, bool POOL, int LAYER, int NIMG, bool WREG>
__global__ void __launch_bounds__(256) bconv2_kernel(
    const float* __restrict__ bn_s, const float* __restrict__ bn_b)
{
    constexpr int CIN = CW * 32;
    constexpr int OH = POOL ? W / 2 : W;
    constexpr int OW = POOL ? W / 2 : W;
    constexpr int G = CW / 4;
    constexpr int COW = COUT / 32;
    constexpr int HP = (W + 2) * (W + 2);
    constexpr bool FINAL = (LAYER == 6);
    constexpr bool PAIR = (!POOL && G == 1);
    constexpr int WSZ = WREG ? 1 : 9 * G * 32;

    const unsigned* in_bits;
    const unsigned* wp;
    unsigned* outb = nullptr;
    if constexpr (LAYER == 2)      { in_bits = g_bits1; wp = g_pw2; outb = g_bits2; }
    else if constexpr (LAYER == 3) { in_bits = g_bits2; wp = g_pw3; outb = g_bits3; }
    else if constexpr (LAYER == 4) { in_bits = g_bits3; wp = g_pw4; outb = g_bits4; }
    else if constexpr (LAYER == 5) { in_bits = g_bits4; wp = g_pw5; outb = g_bits5; }
    else                           { in_bits = g_bits5; wp = g_pw6; }

    __shared__ __align__(16) unsigned act[2][HP * CW];
    __shared__ __align__(16) uint4 wsm[WSZ];

    const int tid = threadIdx.x, lane = tid & 31, warp = tid >> 5;
    const int cog = blockIdx.x;
    const int img0 = blockIdx.y * NIMG;
    const int co = cog * 32 + lane;

    const uint4* pw4 = reinterpret_cast<const uint4*>(wp);

    // ---- weights ----
    uint4 wv[WREG ? 9 * G : 1];
    if constexpr (WREG) {
#pragma unroll
        for (int t = 0; t < 9; t++)
#pragma unroll
            for (int g = 0; g < G; g++)
                wv[t * G + g] = pw4[(t * G + g) * COUT + co];
    } else {
        for (int i = tid; i < 9 * G * 32; i += 256) {
            int l = i & 31, q = i >> 5;
            wsm[i] = pw4[q * COUT + cog * 32 + l];
        }
    }

    // ---- zero both act buffers (halo stays 0 forever) ----
    for (int i = tid; i < 2 * HP * CW; i += 256)
        reinterpret_cast<unsigned*>(act)[i] = 0;
    __syncthreads();

    // ---- per-tap weight sign sums ----
    int S[9];
#pragma unroll
    for (int t = 0; t < 9; t++) {
        int p = 0;
#pragma unroll
        for (int g = 0; g < G; g++) {
            uint4 w = WREG ? wv[t * G + g] : wsm[(t * G + g) * 32 + lane];
            p += __popc(w.x) + __popc(w.y) + __popc(w.z) + __popc(w.w);
        }
        S[t] = CIN - 2 * p;
    }
    const float scale = bn_s[co], bias = bn_b[co];

    // ---- prefetch image img0 into buffer 0 ----
    {
        const uint4* src = reinterpret_cast<const uint4*>(in_bits) + (size_t)img0 * W * W * G;
        u32 sbase = (u32)__cvta_generic_to_shared(act[0]);
        for (int i = tid; i < W * W * G; i += 256) {
            int g = i % G, q = i / G;
            int x = q % W, y = q / W;
            cp16(sbase + (u32)((((y + 1) * (W + 2) + (x + 1)) * G + g) * 16), src + i);
        }
        CP_COMMIT();
    }

    for (int bi = 0; bi < NIMG; bi++) {
        CP_WAIT0();
        __syncthreads();
        if (bi + 1 < NIMG) {
            const uint4* src = reinterpret_cast<const uint4*>(in_bits)
                               + (size_t)(img0 + bi + 1) * W * W * G;
            u32 sbase = (u32)__cvta_generic_to_shared(act[(bi + 1) & 1]);
            for (int i = tid; i < W * W * G; i += 256) {
                int g = i % G, q = i / G;
                int x = q % W, y = q / W;
                cp16(sbase + (u32)((((y + 1) * (W + 2) + (x + 1)) * G + g) * 16), src + i);
            }
            CP_COMMIT();
        }

        const uint4* A = reinterpret_cast<const uint4*>(act[bi & 1]);
        const int b = img0 + bi;

        if constexpr (POOL) {
            for (int op = warp; op < OH * OW; op += 8) {
                const int oy = op / OW, ox = op % OW;
                const int iy = 2 * oy, ix = 2 * ox;
                int p00 = 0, p01 = 0, p10 = 0, p11 = 0;
#pragma unroll
                for (int g = 0; g < G; g++) {
                    uint4 w9[9];
#pragma unroll
                    for (int t = 0; t < 9; t++)
                        w9[t] = WREG ? wv[t * G + g] : wsm[(t * G + g) * 32 + lane];
                    const uint4* P = A + (iy * (W + 2) + ix) * G + g;
#pragma unroll
                    for (int r = 0; r < 4; r++) {
                        uint4 a0 = P[(r * (W + 2) + 0) * G];
                        uint4 a1 = P[(r * (W + 2) + 1) * G];
                        uint4 a2 = P[(r * (W + 2) + 2) * G];
                        uint4 a3 = P[(r * (W + 2) + 3) * G];
                        if (r < 3) {
                            p00 += popc4x(a0, w9[r * 3 + 0]) + popc4x(a1, w9[r * 3 + 1]) + popc4x(a2, w9[r * 3 + 2]);
                            p01 += popc4x(a1, w9[r * 3 + 0]) + popc4x(a2, w9[r * 3 + 1]) + popc4x(a3, w9[r * 3 + 2]);
                        }
                        if (r > 0) {
                            p10 += popc4x(a0, w9[(r - 1) * 3 + 0]) + popc4x(a1, w9[(r - 1) * 3 + 1]) + popc4x(a2, w9[(r - 1) * 3 + 2]);
                            p11 += popc4x(a1, w9[(r - 1) * 3 + 0]) + popc4x(a2, w9[(r - 1) * 3 + 1]) + popc4x(a3, w9[(r - 1) * 3 + 2]);
                        }
                    }
                }
                int s0 = 9 * CIN - 2 * p00 - border_corr(iy,     ix,     W, W, S);
                int s1 = 9 * CIN - 2 * p01 - border_corr(iy,     ix + 1, W, W, S);
                int s2 = 9 * CIN - 2 * p10 - border_corr(iy + 1, ix,     W, W, S);
                int s3 = 9 * CIN - 2 * p11 - border_corr(iy + 1, ix + 1, W, W, S);
                int m = max(0, max(max(s0, s1), max(s2, s3)));
                if constexpr (FINAL) {
                    g_h6[((b * OH + oy) * OW + ox) * COUT + co] = fmaf((float)m, scale, bias);
                } else {
                    bool bit = fmaf((float)m, scale, bias) > 0.f;
                    unsigned wd = __ballot_sync(0xffffffffu, bit);
                    if (lane == 0) outb[((b * OH + oy) * OW + ox) * COW + cog] = wd;
                }
            }
        } else if constexpr (PAIR) {
            // pixel pairs (ox even): 12 act loads serve 2 outputs, G==1
            for (int pp = warp; pp < W * W / 2; pp += 8) {
                const int oy = pp / (W / 2), ox = 2 * (pp % (W / 2));
                uint4 l[12];
#pragma unroll
                for (int r = 0; r < 3; r++)
#pragma unroll
                    for (int c = 0; c < 4; c++)
                        l[r * 4 + c] = A[(oy + r) * (W + 2) + ox + c];
                int a0 = 0, a1 = 0, b0 = 0, b1 = 0;
#pragma unroll
                for (int r = 0; r < 3; r++) {
                    a0 += popc4x(l[r * 4 + 0], wv[r * 3 + 0]) + popc4x(l[r * 4 + 1], wv[r * 3 + 1]);
                    a1 += popc4x(l[r * 4 + 2], wv[r * 3 + 2]);
                    b0 += popc4x(l[r * 4 + 1], wv[r * 3 + 0]) + popc4x(l[r * 4 + 2], wv[r * 3 + 1]);
                    b1 += popc4x(l[r * 4 + 3], wv[r * 3 + 2]);
                }
                int s0 = 9 * CIN - 2 * (a0 + a1) - border_corr(oy, ox,     W, W, S);
                int s1 = 9 * CIN - 2 * (b0 + b1) - border_corr(oy, ox + 1, W, W, S);
                bool bit0 = fmaf((float)max(s0, 0), scale, bias) > 0.f;
                bool bit1 = fmaf((float)max(s1, 0), scale, bias) > 0.f;
                unsigned w0 = __ballot_sync(0xffffffffu, bit0);
                unsigned w1 = __ballot_sync(0xffffffffu, bit1);
                if (lane == 0) {
                    outb[((b * W + oy) * W + ox) * COW + cog] = w0;
                    outb[((b * W + oy) * W + ox + 1) * COW + cog] = w1;
                }
            }
        } else {
            // non-pool, G>=2, weights in smem
            for (int op = warp; op < W * W; op += 8) {
                const int oy = op / W, ox = op % W;
                const uint4* P = A + (oy * (W + 2) + ox) * G;
                int a0 = 0, a1 = 0, a2 = 0, a3 = 0;
#pragma unroll
                for (int g = 0; g < G; g++) {
                    uint4 aa[9];
#pragma unroll
                    for (int r = 0; r < 3; r++)
#pragma unroll
                        for (int c = 0; c < 3; c++)
                            aa[r * 3 + c] = P[(r * (W + 2) + c) * G + g];
                    a0 += popc4x(aa[0], wsm[(0 * G + g) * 32 + lane]);
                    a1 += popc4x(aa[1], wsm[(1 * G + g) * 32 + lane]);
                    a2 += popc4x(aa[2], wsm[(2 * G + g) * 32 + lane]);
                    a3 += popc4x(aa[3], wsm[(3 * G + g) * 32 + lane]);
                    a0 += popc4x(aa[4], wsm[(4 * G + g) * 32 + lane]);
                    a1 += popc4x(aa[5], wsm[(5 * G + g) * 32 + lane]);
                    a2 += popc4x(aa[6], wsm[(6 * G + g) * 32 + lane]);
                    a3 += popc4x(aa[7], wsm[(7 * G + g) * 32 + lane]);
                    a0 += popc4x(aa[8], wsm[(8 * G + g) * 32 + lane]);
                }
                int acc = (a0 + a1) + (a2 + a3);
                int s = 9 * CIN - 2 * acc - border_corr(oy, ox, W, W, S);
                bool bit = fmaf((float)max(s, 0), scale, bias) > 0.f;
                unsigned wd = __ballot_sync(0xffffffffu, bit);
                if (lane == 0) outb[((b * W + oy) * W + ox) * COW + cog] = wd;
            }
        }
    }
}

// ---------------------------------------------------------------------------
// Dense (512->10 on last axis) + bias + softmax
// ---------------------------------------------------------------------------
__global__ void __launch_bounds__(128) dense_softmax_kernel(
    const float* __restrict__ dw, const float* __restrict__ db, float* __restrict__ out)
{
    __shared__ float sdw[512 * 10];
    __shared__ float sdb[10];
    int tid = threadIdx.x;
    for (int i = tid; i < 5120; i += 128) sdw[i] = dw[i];
    if (tid < 10) sdb[tid] = db[tid];
    __syncthreads();

    int r = blockIdx.x * 128 + tid;
    float acc[10];
#pragma unroll
    for (int d = 0; d < 10; d++) acc[d] = sdb[d];
    const float* h = g_h6 + (size_t)r * 512;
    for (int c = 0; c < 512; c++) {
        float hv = h[c];
#pragma unroll
        for (int d = 0; d < 10; d++) acc[d] = fmaf(hv, sdw[c * 10 + d], acc[d]);
    }
    float m = acc[0];
#pragma unroll
    for (int d = 1; d < 10; d++) m = fmaxf(m, acc[d]);
    float e[10], s = 0.f;
#pragma unroll
    for (int d = 0; d < 10; d++) { e[d] = expf(acc[d] - m); s += e[d]; }
    float inv = 1.f / s;
#pragma unroll
    for (int d = 0; d < 10; d++) out[r * 10 + d] = e[d] * inv;
}

// ---------------------------------------------------------------------------
// Launch
// ---------------------------------------------------------------------------
extern "C" void kernel_launch(void* const* d_in, const int* in_sizes, int n_in,
                              void* d_out, int out_size)
{
    const float *x = nullptr, *w1 = nullptr, *b1 = nullptr;
    const float *w2 = nullptr, *w3 = nullptr, *w4 = nullptr, *w5 = nullptr, *w6 = nullptr;
    const float *dw = nullptr, *db = nullptr;
    const float* bns[12] = {nullptr};
    int bn_idx = 0;

    for (int i = 0; i < n_in; i++) {
        const float* p = (const float*)d_in[i];
        int s = in_sizes[i];
        if (i == 0)              x = p;
        else if (s == 3456)      w1 = p;
        else if (i == 2)         b1 = p;
        else if (s == 147456)    w2 = p;
        else if (s == 294912)    w3 = p;
        else if (s == 589824)    w4 = p;
        else if (s == 1179648)   w5 = p;
        else if (s == 2359296)   w6 = p;
        else if (s == 5120)      dw = p;
        else if (s == 10)        db = p;
        else if (bn_idx < 12)    bns[bn_idx++] = p;
    }

    conv1_kernel<<<1024, 128>>>(x, w1, b1, bns[0], bns[1]);
    pack_all_kernel<<<(142848 + 255) / 256, 256>>>(w2, w3, w4, w5, w6);

    // <W, CW, COUT, POOL, LAYER, NIMG, WREG>   grid = (cout_groups, 128/NIMG)
    bconv2_kernel<32, 4, 128, true,  2, 2, true ><<<dim3(4, 64), 256>>>(bns[2], bns[3]);
    bconv2_kernel<16, 4, 256, false, 3, 2, true ><<<dim3(8, 64), 256>>>(bns[4], bns[5]);
    bconv2_kernel<16, 8, 256, true,  4, 2, false><<<dim3(8, 64), 256>>>(bns[6], bns[7]);
    bconv2_kernel<8, 8, 512, false, 5, 4, false><<<dim3(16, 32), 256>>>(bns[8], bns[9]);
    bconv2_kernel<8, 16, 512, true,  6, 4, false><<<dim3(16, 32), 256>>>(bns[10], bns[11]);

    dense_softmax_kernel<<<16, 128>>>(dw, db, (float*)d_out);
    (void)out_size;
}